// round 1
// baseline (speedup 1.0000x reference)
#include <cuda_runtime.h>
#include <cstdint>

#define NTOK 16384
#define KDIM 1024

// Scratch: 9 projection buffers + averaged attention output (static device mem; no allocs).
static __device__ float g_P[9][(size_t)NTOK * KDIM];   // 576 MB
static __device__ float g_avg[(size_t)NTOK * KDIM];    // 64 MB

// Buffer map:
// 0:Q1  1:V2  2:K3  3:K2  4:V1  5:Q3  6:Q2  7:K1  8:V3
// attn1: Q=0 K=7 V=4 | attn2: Q=6 K=3 V=1 | attn3: Q=5 K=2 V=8

struct GemmJob { const float* X; const float* W; const float* Bv; float* C; };
struct GemmArgs { GemmJob job[9]; int relu; };

__device__ __forceinline__ uint32_t f2tf32(float f) {
    uint32_t r;
    asm("cvt.rna.tf32.f32 %0, %1;" : "=r"(r) : "f"(f));
    return r;
}

// ---------------------------------------------------------------------------
// TF32 GEMM: C[n,j] = sum_k X[n,k] * W[j,k] + Bv[j]  (optional ReLU)
// Tiles: BM=128, BN=128, BK=32. 256 threads (8 warps in 2x4 grid; 64x32/warp).
// Smem layout [row][36] (BK=32 + pad 4): conflict-free for both the
// STS.128 tile stores and the m16n8k8 fragment LDS pattern (bank = 4*m + k mod 32).
// ---------------------------------------------------------------------------
__global__ __launch_bounds__(256, 2)
void gemm_tf32_kernel(GemmArgs ga)
{
    GemmJob jb = ga.job[blockIdx.z];
    const float* __restrict__ X = jb.X;
    const float* __restrict__ W = jb.W;

    __shared__ uint32_t As[128][36];
    __shared__ uint32_t Bs[128][36];

    const int tid  = threadIdx.x;
    const int lane = tid & 31;
    const int warp = tid >> 5;
    const int wm   = warp & 1;     // 0..1 (64 rows each)
    const int wn   = warp >> 1;    // 0..3 (32 cols each)
    const int rowBase = blockIdx.y * 128;
    const int colBase = blockIdx.x * 128;

    float acc[4][4][4];
#pragma unroll
    for (int i = 0; i < 4; i++)
#pragma unroll
        for (int j = 0; j < 4; j++)
#pragma unroll
            for (int k = 0; k < 4; k++) acc[i][j][k] = 0.f;

    const int lr = tid >> 3;          // 0..31
    const int lk = (tid & 7) << 2;    // 0,4,...,28

    for (int kb = 0; kb < KDIM; kb += 32) {
#pragma unroll
        for (int i = 0; i < 4; i++) {
            int r = lr + 32 * i;
            float4 v = *reinterpret_cast<const float4*>(
                X + (size_t)(rowBase + r) * KDIM + kb + lk);
            uint4 u = make_uint4(f2tf32(v.x), f2tf32(v.y), f2tf32(v.z), f2tf32(v.w));
            *reinterpret_cast<uint4*>(&As[r][lk]) = u;
        }
#pragma unroll
        for (int i = 0; i < 4; i++) {
            int r = lr + 32 * i;
            float4 v = *reinterpret_cast<const float4*>(
                W + (size_t)(colBase + r) * KDIM + kb + lk);
            uint4 u = make_uint4(f2tf32(v.x), f2tf32(v.y), f2tf32(v.z), f2tf32(v.w));
            *reinterpret_cast<uint4*>(&Bs[r][lk]) = u;
        }
        __syncthreads();

#pragma unroll
        for (int ks = 0; ks < 4; ks++) {
            const int k0 = ks * 8 + (lane & 3);
            uint32_t a[4][4], b[4][2];
#pragma unroll
            for (int mt = 0; mt < 4; mt++) {
                int m0 = wm * 64 + mt * 16 + (lane >> 2);
                a[mt][0] = As[m0    ][k0    ];
                a[mt][1] = As[m0 + 8][k0    ];
                a[mt][2] = As[m0    ][k0 + 4];
                a[mt][3] = As[m0 + 8][k0 + 4];
            }
#pragma unroll
            for (int nt = 0; nt < 4; nt++) {
                int n0 = wn * 32 + nt * 8 + (lane >> 2);
                b[nt][0] = Bs[n0][k0    ];
                b[nt][1] = Bs[n0][k0 + 4];
            }
#pragma unroll
            for (int mt = 0; mt < 4; mt++)
#pragma unroll
                for (int nt = 0; nt < 4; nt++)
                    asm volatile(
                        "mma.sync.aligned.m16n8k8.row.col.f32.tf32.tf32.f32 "
                        "{%0,%1,%2,%3},{%4,%5,%6,%7},{%8,%9},{%0,%1,%2,%3};"
                        : "+f"(acc[mt][nt][0]), "+f"(acc[mt][nt][1]),
                          "+f"(acc[mt][nt][2]), "+f"(acc[mt][nt][3])
                        : "r"(a[mt][0]), "r"(a[mt][1]), "r"(a[mt][2]), "r"(a[mt][3]),
                          "r"(b[nt][0]), "r"(b[nt][1]));
        }
        __syncthreads();
    }

    const float* __restrict__ Bv = jb.Bv;
    float* __restrict__ C = jb.C;
    const int rg = lane >> 2;
    const int cg = (lane & 3) << 1;
#pragma unroll
    for (int mt = 0; mt < 4; mt++) {
#pragma unroll
        for (int nt = 0; nt < 4; nt++) {
            int row = rowBase + wm * 64 + mt * 16 + rg;
            int col = colBase + wn * 32 + nt * 8 + cg;
            float b0 = Bv[col], b1 = Bv[col + 1];
            float2 v0 = make_float2(acc[mt][nt][0] + b0, acc[mt][nt][1] + b1);
            float2 v1 = make_float2(acc[mt][nt][2] + b0, acc[mt][nt][3] + b1);
            if (ga.relu) {
                v0.x = fmaxf(v0.x, 0.f); v0.y = fmaxf(v0.y, 0.f);
                v1.x = fmaxf(v1.x, 0.f); v1.y = fmaxf(v1.y, 0.f);
            }
            *reinterpret_cast<float2*>(C + (size_t)row * KDIM + col) = v0;
            *reinterpret_cast<float2*>(C + (size_t)(row + 8) * KDIM + col) = v1;
        }
    }
}

// ---------------------------------------------------------------------------
// Per-token attention (fp32). One CTA (128 thr) per token; 3 attentions:
//   Q[d,h] = P_q[n, h*64+d]  (d,e in [0,64), h in [0,16))
//   S[d,e] = (1/8) sum_h Q[d,h] K[e,h];  softmax over d (per column e);
//   O[d,h] = sum_e w[d,e] V[e,h];  out[n, h*64+d] += O   ; avg /3 at end.
// 1/colsum is folded into V to avoid renormalizing S.
// ---------------------------------------------------------------------------
__global__ __launch_bounds__(128)
void attn_kernel()
{
    __shared__ float Qs[1024], Ks[1024], Vs[1024];
    __shared__ float S[64][65];
    __shared__ float recip[64];

    const int n   = blockIdx.x;
    const int tid = threadIdx.x;
    const size_t off = (size_t)n * KDIM;

    const int QI[3] = {0, 6, 5};
    const int KI[3] = {7, 3, 2};
    const int VI[3] = {4, 1, 8};

    // S-phase mapping: 4 d-rows x 8 e-cols per thread
    const int d0 = (tid >> 3) << 2;   // 0..60
    const int e0 = (tid & 7) << 3;    // 0..56
    // O-phase mapping: d in {lane, lane+32}, 4 heads per thread
    const int lane = tid & 31;
    const int hq   = (tid >> 5) << 2; // 0,4,8,12

    float out[2][4];
#pragma unroll
    for (int i = 0; i < 2; i++)
#pragma unroll
        for (int j = 0; j < 4; j++) out[i][j] = 0.f;

    for (int a = 0; a < 3; a++) {
        const float4* q4 = reinterpret_cast<const float4*>(g_P[QI[a]] + off);
        const float4* k4 = reinterpret_cast<const float4*>(g_P[KI[a]] + off);
        const float4* v4 = reinterpret_cast<const float4*>(g_P[VI[a]] + off);
#pragma unroll
        for (int i = 0; i < 2; i++) {
            reinterpret_cast<float4*>(Qs)[tid + 128 * i] = q4[tid + 128 * i];
            reinterpret_cast<float4*>(Ks)[tid + 128 * i] = k4[tid + 128 * i];
            reinterpret_cast<float4*>(Vs)[tid + 128 * i] = v4[tid + 128 * i];
        }
        __syncthreads();

        // S = Q K^T / 8
        float sacc[4][8];
#pragma unroll
        for (int i = 0; i < 4; i++)
#pragma unroll
            for (int j = 0; j < 8; j++) sacc[i][j] = 0.f;
        for (int h = 0; h < 16; h++) {
            float qv[4], kv[8];
#pragma unroll
            for (int j = 0; j < 4; j++) qv[j] = Qs[h * 64 + d0 + j];
#pragma unroll
            for (int j = 0; j < 8; j++) kv[j] = Ks[h * 64 + e0 + j];
#pragma unroll
            for (int i = 0; i < 4; i++)
#pragma unroll
                for (int j = 0; j < 8; j++) sacc[i][j] += qv[i] * kv[j];
        }
#pragma unroll
        for (int i = 0; i < 4; i++)
#pragma unroll
            for (int j = 0; j < 8; j++) S[d0 + i][e0 + j] = sacc[i][j] * 0.125f;
        __syncthreads();

        // softmax over d for each column e (threads 0..63)
        if (tid < 64) {
            const int e = tid;
            float m = -1e30f;
            for (int d = 0; d < 64; d++) m = fmaxf(m, S[d][e]);
            float s = 0.f;
            for (int d = 0; d < 64; d++) {
                float w = __expf(S[d][e] - m);
                S[d][e] = w;
                s += w;
            }
            recip[e] = 1.f / s;
        }
        __syncthreads();

        // fold 1/sum into V: V[e,h] stored at Vs[h*64+e]
#pragma unroll
        for (int i = 0; i < 8; i++) {
            int j = tid + 128 * i;
            Vs[j] *= recip[j & 63];
        }
        __syncthreads();

        // O[d,h] = sum_e S[d,e] * V'[e,h]
        float oacc[2][4];
#pragma unroll
        for (int i = 0; i < 2; i++)
#pragma unroll
            for (int j = 0; j < 4; j++) oacc[i][j] = 0.f;
        for (int e = 0; e < 64; e++) {
            float s0 = S[lane     ][e];
            float s1 = S[lane + 32][e];
#pragma unroll
            for (int hh = 0; hh < 4; hh++) {
                float v = Vs[(hq + hh) * 64 + e];
                oacc[0][hh] += s0 * v;
                oacc[1][hh] += s1 * v;
            }
        }
#pragma unroll
        for (int i = 0; i < 2; i++)
#pragma unroll
            for (int hh = 0; hh < 4; hh++) out[i][hh] += oacc[i][hh];
        __syncthreads();  // protect smem before next attention's loads
    }

    float* dst = g_avg + off;
#pragma unroll
    for (int hh = 0; hh < 4; hh++) {
        dst[(hq + hh) * 64 + lane     ] = out[0][hh] * (1.f / 3.f);
        dst[(hq + hh) * 64 + lane + 32] = out[1][hh] * (1.f / 3.f);
    }
}

// ---------------------------------------------------------------------------
// d_in order: 0 query, 1 key, 2 value, 3 Wq1, 4 bq1, 5 Wk1, 6 bk1, 7 Wv1, 8 bv1,
// 9 Wq2, 10 bq2, 11 Wk2, 12 bk2, 13 Wv2, 14 bv2, 15 Wq3, 16 bq3, 17 Wk3, 18 bk3,
// 19 Wv3, 20 bv3, 21 Wo, 22 bo
// Cross-wiring (per reference):
//   Q1=q*Wq1  V2=q*Wv2  K3=q*Wk3 | K2=k*Wk1  V1=k*Wv1  Q3=k*Wq3 | Q2=v*Wq2  K1=v*Wk2  V3=v*Wv3
// ---------------------------------------------------------------------------
extern "C" void kernel_launch(void* const* d_in, const int* in_sizes, int n_in,
                              void* d_out, int out_size)
{
    (void)in_sizes; (void)n_in; (void)out_size;

    const float* query = (const float*)d_in[0];
    const float* key   = (const float*)d_in[1];
    const float* value = (const float*)d_in[2];
    const float* Wo    = (const float*)d_in[21];
    const float* bo    = (const float*)d_in[22];

    float* P0 = nullptr; float* AVG = nullptr;
    cudaGetSymbolAddress((void**)&P0, g_P);
    cudaGetSymbolAddress((void**)&AVG, g_avg);

    const float* xs[9]  = { query, query, query, key, key, key, value, value, value };
    const int    widx[9] = { 3, 13, 17, 5, 7, 15, 9, 11, 19 };

    GemmArgs pa;
    for (int i = 0; i < 9; i++) {
        pa.job[i].X  = xs[i];
        pa.job[i].W  = (const float*)d_in[widx[i]];
        pa.job[i].Bv = (const float*)d_in[widx[i] + 1];
        pa.job[i].C  = P0 + (size_t)i * NTOK * KDIM;
    }
    pa.relu = 0;
    gemm_tf32_kernel<<<dim3(KDIM / 128, NTOK / 128, 9), 256>>>(pa);

    attn_kernel<<<NTOK, 128>>>();

    GemmArgs fa;
    for (int i = 0; i < 9; i++) {
        fa.job[i].X  = AVG;
        fa.job[i].W  = Wo;
        fa.job[i].Bv = bo;
        fa.job[i].C  = (float*)d_out;
    }
    fa.relu = 1;
    gemm_tf32_kernel<<<dim3(KDIM / 128, NTOK / 128, 1), 256>>>(fa);
}

// round 4
// speedup vs baseline: 1.5751x; 1.5751x over previous
#include <cuda_runtime.h>
#include <cuda_fp16.h>
#include <cstdint>

#define NTOK 16384
#define KDIM 1024
#define BM 128
#define BN 128
#define BK 32
#define NSTAGE 3
#define NKIT (KDIM / BK)

// Smem stage geometry (halves): row = 32 data + 8 pad = 40 halves = 80 bytes.
// A tile 128 rows (10240 B) + B tile 128 rows (10240 B) = 20480 B per stage.
#define ROW_B 80
#define ROW_W 20                      // 32-bit words per row
#define STAGE_B 20480
#define SMEM_DYN (NSTAGE * STAGE_B)   // 61440

// Scratch (static device memory; no allocs):
static __device__ float  g_P[9][(size_t)NTOK * KDIM];    // projection outputs (fp32)
static __device__ __half g_Xh[3][(size_t)NTOK * KDIM];   // fp16-rounded q,k,v
static __device__ __half g_Wh[10][(size_t)KDIM * KDIM];  // fp16-rounded weights
static __device__ __half g_avgh[(size_t)NTOK * KDIM];    // averaged attn out (fp16)

// Buffer map: 0:Q1 1:V2 2:K3 3:K2 4:V1 5:Q3 6:Q2 7:K1 8:V3
// attn1: Q=0 K=7 V=4 | attn2: Q=6 K=3 V=1 | attn3: Q=5 K=2 V=8

struct GemmJob { const __half* X; const __half* W; const float* Bv; float* C; };
struct GemmArgs { GemmJob job[9]; int relu; };
struct RJob { const float* s; __half* d; int n4; };
struct RArgs { RJob j[13]; };

__device__ __forceinline__ uint32_t smem_u32(const void* p) {
    uint32_t a;
    asm("{ .reg .u64 t; cvta.to.shared.u64 t, %1; cvt.u32.u64 %0, t; }" : "=r"(a) : "l"(p));
    return a;
}
__device__ __forceinline__ uint32_t h2_u32(__half2 h) {
    uint32_t u;
    memcpy(&u, &h, 4);
    return u;
}
#define CP_ASYNC16(dst, src) \
    asm volatile("cp.async.cg.shared.global [%0], [%1], 16;" :: "r"(dst), "l"(src))
#define CP_COMMIT() asm volatile("cp.async.commit_group;")
#define CP_WAIT1()  asm volatile("cp.async.wait_group 1;")

// ---------------------------------------------------------------------------
// fp16 GEMM via legacy mma.sync m16n8k16 (fp32 accum):
//   C[n,j] = sum_k X[n,k]*W[j,k] + Bv[j]  (optional ReLU)
// CTA tile 128x128, BK=32, 3-stage cp.async pipeline, 256 thr (8 warps 2x4,
// 64x32 per warp). Padded [40-half] rows are conflict-free for the fragment
// LDS pattern (bank = 20*g + t mod 32, distinct over the warp).
// ---------------------------------------------------------------------------
__device__ __forceinline__ void load_stage(char* sm, int s,
                                           const __half* __restrict__ X,
                                           const __half* __restrict__ W,
                                           int kb, int tid) {
    char* aB = sm + s * STAGE_B;
    char* bB = aB + 10240;
    const int r = tid >> 2;          // 0..63
    const int c = tid & 3;           // 16B chunk
#pragma unroll
    for (int j = 0; j < 2; j++) {
        int rr = r + 64 * j;
        CP_ASYNC16(smem_u32(aB + rr * ROW_B + c * 16),
                   X + (size_t)rr * KDIM + kb + c * 8);
        CP_ASYNC16(smem_u32(bB + rr * ROW_B + c * 16),
                   W + (size_t)rr * KDIM + kb + c * 8);
    }
}

__global__ __launch_bounds__(256, 2)
void gemm_f16(GemmArgs ga)
{
    extern __shared__ __align__(16) char dsm[];
    __shared__ float s_bias[BN];

    const GemmJob jb = ga.job[blockIdx.z];
    const int tid  = threadIdx.x;
    const int lane = tid & 31;
    const int warp = tid >> 5;
    const int wm   = warp & 1;       // 64-row half
    const int wn   = warp >> 1;      // 32-col quarter
    const int rowBase = blockIdx.y * BM;
    const int colBase = blockIdx.x * BN;

    const __half* __restrict__ X = jb.X + (size_t)rowBase * KDIM;
    const __half* __restrict__ W = jb.W + (size_t)colBase * KDIM;

    if (tid < 32)
        *reinterpret_cast<float4*>(&s_bias[tid * 4]) =
            *reinterpret_cast<const float4*>(jb.Bv + colBase + tid * 4);

    float acc[4][4][4];
#pragma unroll
    for (int i = 0; i < 4; i++)
#pragma unroll
        for (int j = 0; j < 4; j++)
#pragma unroll
            for (int k = 0; k < 4; k++) acc[i][j][k] = 0.f;

    // prologue: stages 0,1
    load_stage(dsm, 0, X, W, 0, tid);
    CP_COMMIT();
    load_stage(dsm, 1, X, W, BK, tid);
    CP_COMMIT();

    const int g = lane >> 2;
    const int t = lane & 3;

    for (int i = 0; i < NKIT; i++) {
        const int s = i % NSTAGE;
        CP_WAIT1();
        __syncthreads();

        // prefetch stage i+2 into slot (i+2)%3 (that slot's data was consumed
        // in iter i-1; the barrier above orders all warps past that compute)
        if (i + 2 < NKIT)
            load_stage(dsm, (i + 2) % NSTAGE, X, W, (i + 2) * BK, tid);
        CP_COMMIT();

        const uint32_t* As32 = reinterpret_cast<const uint32_t*>(dsm + s * STAGE_B);
        const uint32_t* Bs32 = reinterpret_cast<const uint32_t*>(dsm + s * STAGE_B + 10240);

#pragma unroll
        for (int ks2 = 0; ks2 < 2; ks2++) {   // two K=16 slabs
            const int kw = ks2 * 8 + t;
            uint32_t a[4][4], b[4][2];
#pragma unroll
            for (int mt = 0; mt < 4; mt++) {
                int m0 = wm * 64 + mt * 16 + g;
                a[mt][0] = As32[m0 * ROW_W + kw];
                a[mt][1] = As32[(m0 + 8) * ROW_W + kw];
                a[mt][2] = As32[m0 * ROW_W + kw + 4];
                a[mt][3] = As32[(m0 + 8) * ROW_W + kw + 4];
            }
#pragma unroll
            for (int nt = 0; nt < 4; nt++) {
                int n0 = wn * 32 + nt * 8 + g;
                b[nt][0] = Bs32[n0 * ROW_W + kw];
                b[nt][1] = Bs32[n0 * ROW_W + kw + 4];
            }
#pragma unroll
            for (int mt = 0; mt < 4; mt++)
#pragma unroll
                for (int nt = 0; nt < 4; nt++)
                    asm volatile(
                        "mma.sync.aligned.m16n8k16.row.col.f32.f16.f16.f32 "
                        "{%0,%1,%2,%3},{%4,%5,%6,%7},{%8,%9},{%0,%1,%2,%3};"
                        : "+f"(acc[mt][nt][0]), "+f"(acc[mt][nt][1]),
                          "+f"(acc[mt][nt][2]), "+f"(acc[mt][nt][3])
                        : "r"(a[mt][0]), "r"(a[mt][1]), "r"(a[mt][2]), "r"(a[mt][3]),
                          "r"(b[nt][0]), "r"(b[nt][1]));
        }
    }

    // Epilogue
    const int relu = ga.relu;
    float* __restrict__ C = jb.C;
    const int rg = g;
    const int cg = t << 1;
#pragma unroll
    for (int mt = 0; mt < 4; mt++) {
#pragma unroll
        for (int nt = 0; nt < 4; nt++) {
            int row = rowBase + wm * 64 + mt * 16 + rg;
            int col = colBase + wn * 32 + nt * 8 + cg;
            float b0 = s_bias[col - colBase], b1 = s_bias[col - colBase + 1];
            float2 v0 = make_float2(acc[mt][nt][0] + b0, acc[mt][nt][1] + b1);
            float2 v1 = make_float2(acc[mt][nt][2] + b0, acc[mt][nt][3] + b1);
            if (relu) {
                v0.x = fmaxf(v0.x, 0.f); v0.y = fmaxf(v0.y, 0.f);
                v1.x = fmaxf(v1.x, 0.f); v1.y = fmaxf(v1.y, 0.f);
            }
            *reinterpret_cast<float2*>(C + (size_t)row * KDIM + col) = v0;
            *reinterpret_cast<float2*>(C + (size_t)(row + 8) * KDIM + col) = v1;
        }
    }
}

// ---------------------------------------------------------------------------
// fp32 -> fp16 (RN) conversion, batched over 13 tensors
// ---------------------------------------------------------------------------
__global__ __launch_bounds__(256)
void cvt_kernel(RArgs ra)
{
    RJob jb = ra.j[blockIdx.y];
    const int stride = gridDim.x * blockDim.x;
    for (int i = blockIdx.x * blockDim.x + threadIdx.x; i < jb.n4; i += stride) {
        float4 v = reinterpret_cast<const float4*>(jb.s)[i];
        __half2 h0 = __floats2half2_rn(v.x, v.y);
        __half2 h1 = __floats2half2_rn(v.z, v.w);
        reinterpret_cast<uint2*>(jb.d)[i] = make_uint2(h2_u32(h0), h2_u32(h1));
    }
}

// ---------------------------------------------------------------------------
// Per-token attention (fp32 smem math). One CTA (128 thr) per token, 3 attns:
//   S[d,e] = (1/8) sum_h Q[d,h] K[e,h]; softmax over d per column e;
//   O[d,h] = sum_e w[d,e] V'[e,h] with 1/colsum folded into V.
// Output: fp16 average into g_avgh.
// ---------------------------------------------------------------------------
__global__ __launch_bounds__(128)
void attn_kernel()
{
    __shared__ float Qs[1024], Ks[1024], Vs[1024];
    __shared__ float S[64][65];
    __shared__ float recip[64];

    const int n   = blockIdx.x;
    const int tid = threadIdx.x;
    const size_t off = (size_t)n * KDIM;

    const int QI[3] = {0, 6, 5};
    const int KI[3] = {7, 3, 2};
    const int VI[3] = {4, 1, 8};

    const int d0 = (tid >> 3) << 2;
    const int e0 = (tid & 7) << 3;
    const int lane = tid & 31;
    const int hq   = (tid >> 5) << 2;

    float out[2][4];
#pragma unroll
    for (int i = 0; i < 2; i++)
#pragma unroll
        for (int j = 0; j < 4; j++) out[i][j] = 0.f;

    for (int a = 0; a < 3; a++) {
        const float4* q4 = reinterpret_cast<const float4*>(g_P[QI[a]] + off);
        const float4* k4 = reinterpret_cast<const float4*>(g_P[KI[a]] + off);
        const float4* v4 = reinterpret_cast<const float4*>(g_P[VI[a]] + off);
#pragma unroll
        for (int i = 0; i < 2; i++) {
            reinterpret_cast<float4*>(Qs)[tid + 128 * i] = q4[tid + 128 * i];
            reinterpret_cast<float4*>(Ks)[tid + 128 * i] = k4[tid + 128 * i];
            reinterpret_cast<float4*>(Vs)[tid + 128 * i] = v4[tid + 128 * i];
        }
        __syncthreads();

        float sacc[4][8];
#pragma unroll
        for (int i = 0; i < 4; i++)
#pragma unroll
            for (int j = 0; j < 8; j++) sacc[i][j] = 0.f;
        for (int h = 0; h < 16; h++) {
            float qv[4], kv[8];
#pragma unroll
            for (int j = 0; j < 4; j++) qv[j] = Qs[h * 64 + d0 + j];
#pragma unroll
            for (int j = 0; j < 8; j++) kv[j] = Ks[h * 64 + e0 + j];
#pragma unroll
            for (int i = 0; i < 4; i++)
#pragma unroll
                for (int j = 0; j < 8; j++) sacc[i][j] += qv[i] * kv[j];
        }
#pragma unroll
        for (int i = 0; i < 4; i++)
#pragma unroll
            for (int j = 0; j < 8; j++) S[d0 + i][e0 + j] = sacc[i][j] * 0.125f;
        __syncthreads();

        if (tid < 64) {
            const int e = tid;
            float m = -1e30f;
            for (int d = 0; d < 64; d++) m = fmaxf(m, S[d][e]);
            float s = 0.f;
            for (int d = 0; d < 64; d++) {
                float w = __expf(S[d][e] - m);
                S[d][e] = w;
                s += w;
            }
            recip[e] = 1.f / s;
        }
        __syncthreads();

#pragma unroll
        for (int i = 0; i < 8; i++) {
            int j = tid + 128 * i;
            Vs[j] *= recip[j & 63];
        }
        __syncthreads();

        float oacc[2][4];
#pragma unroll
        for (int i = 0; i < 2; i++)
#pragma unroll
            for (int j = 0; j < 4; j++) oacc[i][j] = 0.f;
        for (int e = 0; e < 64; e++) {
            float s0 = S[lane     ][e];
            float s1 = S[lane + 32][e];
#pragma unroll
            for (int hh = 0; hh < 4; hh++) {
                float v = Vs[(hq + hh) * 64 + e];
                oacc[0][hh] += s0 * v;
                oacc[1][hh] += s1 * v;
            }
        }
#pragma unroll
        for (int i = 0; i < 2; i++)
#pragma unroll
            for (int hh = 0; hh < 4; hh++) out[i][hh] += oacc[i][hh];
        __syncthreads();
    }

    __half* dst = g_avgh + off;
#pragma unroll
    for (int hh = 0; hh < 4; hh++) {
        dst[(hq + hh) * 64 + lane]      = __float2half_rn(out[0][hh] * (1.f / 3.f));
        dst[(hq + hh) * 64 + lane + 32] = __float2half_rn(out[1][hh] * (1.f / 3.f));
    }
}

// ---------------------------------------------------------------------------
// d_in: 0 query 1 key 2 value | 3 Wq1 4 bq1 5 Wk1 6 bk1 7 Wv1 8 bv1
// 9 Wq2 10 bq2 11 Wk2 12 bk2 13 Wv2 14 bv2 | 15 Wq3 16 bq3 17 Wk3 18 bk3
// 19 Wv3 20 bv3 | 21 Wo 22 bo
// Cross-wiring: Q1=q*Wq1 V2=q*Wv2 K3=q*Wk3 | K2=k*Wk1 V1=k*Wv1 Q3=k*Wq3 |
//               Q2=v*Wq2 K1=v*Wk2 V3=v*Wv3
// ---------------------------------------------------------------------------
extern "C" void kernel_launch(void* const* d_in, const int* in_sizes, int n_in,
                              void* d_out, int out_size)
{
    (void)in_sizes; (void)n_in; (void)out_size;

    float*  P0;  cudaGetSymbolAddress((void**)&P0,  g_P);
    __half* X0;  cudaGetSymbolAddress((void**)&X0,  g_Xh);
    __half* W0;  cudaGetSymbolAddress((void**)&W0,  g_Wh);
    __half* AVG; cudaGetSymbolAddress((void**)&AVG, g_avgh);

    // g_Wh order matches buffer map: 0:Wq1 1:Wv2 2:Wk3 3:Wk1 4:Wv1 5:Wq3
    //                                6:Wq2 7:Wk2 8:Wv3 9:Wo
    const int wsrc[10] = {3, 13, 17, 5, 7, 15, 9, 11, 19, 21};

    RArgs ra;
    for (int t = 0; t < 3; t++) {
        ra.j[t].s  = (const float*)d_in[t];
        ra.j[t].d  = X0 + (size_t)t * NTOK * KDIM;
        ra.j[t].n4 = NTOK * KDIM / 4;
    }
    for (int t = 0; t < 10; t++) {
        ra.j[3 + t].s  = (const float*)d_in[wsrc[t]];
        ra.j[3 + t].d  = W0 + (size_t)t * KDIM * KDIM;
        ra.j[3 + t].n4 = KDIM * KDIM / 4;
    }
    cvt_kernel<<<dim3(512, 13), 256>>>(ra);

    cudaFuncSetAttribute(gemm_f16, cudaFuncAttributeMaxDynamicSharedMemorySize,
                         SMEM_DYN);

    // 9 projections
    const int xsel[9] = {0, 0, 0, 1, 1, 1, 2, 2, 2};
    GemmArgs pa;
    for (int i = 0; i < 9; i++) {
        pa.job[i].X  = X0 + (size_t)xsel[i] * NTOK * KDIM;
        pa.job[i].W  = W0 + (size_t)i * KDIM * KDIM;
        pa.job[i].Bv = (const float*)d_in[wsrc[i] + 1];
        pa.job[i].C  = P0 + (size_t)i * NTOK * KDIM;
    }
    pa.relu = 0;
    gemm_f16<<<dim3(KDIM / BN, NTOK / BM, 9), 256, SMEM_DYN>>>(pa);

    attn_kernel<<<NTOK, 128>>>();

    // output projection + bias + ReLU
    GemmArgs fa;
    for (int i = 0; i < 9; i++) {
        fa.job[i].X  = AVG;
        fa.job[i].W  = W0 + (size_t)9 * KDIM * KDIM;
        fa.job[i].Bv = (const float*)d_in[22];
        fa.job[i].C  = (float*)d_out;
    }
    fa.relu = 1;
    gemm_f16<<<dim3(KDIM / BN, NTOK / BM, 1), 256, SMEM_DYN>>>(fa);
}